// round 6
// baseline (speedup 1.0000x reference)
#include <cuda_runtime.h>
#include <cstdint>

#define GRID1   20
#define NCPAD   8192
#define KC      24             // per-row candidate cap (verified: identical to brute force)
#define CSTRIDE 32
#define MAXM    8192
#define MAXN    8192
#define GBLK    128
#define TBLK    256

typedef unsigned long long u64;

// ---------------- device scratch (no allocations allowed) ----------------
__device__ int            g_cellstart[NCPAD + 1];
__device__ int            g_cellof[MAXN];
__device__ float4         g_cellxyz[MAXN];           // (x,y,z,bitcast id), cell-grouped
__device__ uint4          g_row[MAXM];               // cnt | first 7 sorted candidates
__device__ unsigned short g_sorted[MAXM * CSTRIDE];  // overflow (pos >= 7)
__device__ int            g_owner[MAXN];
__device__ unsigned char  g_ptr[MAXM];
__device__ unsigned short g_queue[MAXM];             // ring (<=1 outstanding per row)
__device__ int            g_qtail;
__device__ float          g_acc[5];
__device__ volatile unsigned g_bcnt[8];              // zero-init; self-resetting
__device__ volatile unsigned g_bgen[8];              // monotonic generation

__device__ __forceinline__ int cell1(float x) {
    int c = (int)floorf(x * 0.2f);
    return min(max(c, 0), GRID1 - 1);
}

// Generation-based grid barrier: count self-resets (last arriver), generation
// is monotonic so no reset race across graph replays. All GBLK blocks are
// co-resident (128 blocks, 32KB smem, 256 thr each) => no deadlock.
__device__ __forceinline__ void gsync(int k) {
    __syncthreads();
    if (threadIdx.x == 0) {
        unsigned old = g_bgen[k];
        __threadfence();
        unsigned a = atomicAdd((unsigned*)&g_bcnt[k], 1u);
        if (a == GBLK - 1) {
            g_bcnt[k] = 0;            // all arrived; safe to reset
            __threadfence();
            atomicAdd((unsigned*)&g_bgen[k], 1u);
        } else {
            while (g_bgen[k] == old) __nanosleep(64);
        }
    }
    __syncthreads();
    __threadfence();
}

__device__ __forceinline__ int cand_at(uint4 rv, int p, int i) {
    if (p < 7) {
        unsigned w = (p == 0) ? rv.x : (p < 3) ? rv.y : (p < 5) ? rv.z : rv.w;
        int sh = (p == 0) ? 16 : ((p & 1) ? 0 : 16);
        return (int)((w >> sh) & 0xFFFFu);
    }
    return (int)g_sorted[(size_t)i * CSTRIDE + p];
}

__device__ __forceinline__ float sl1(float x) {
    float a = fabsf(x);
    return (a < 1.0f) ? 0.5f * a * a : a - 0.5f;
}

__global__ void __launch_bounds__(TBLK, 1)
fused_kernel(const float* __restrict__ pred, const float* __restrict__ gt,
             int m, int n, float* __restrict__ out) {
    __shared__ int s_buf[NCPAD];       // phase A: hist/cursor; phase C2: owner copy
    __shared__ int s_warp[32];
    __shared__ int s_t;
    int b = blockIdx.x, tid = threadIdx.x;
    int lane = tid & 31, wid = tid >> 5;

    // ================= phase A: build hash (block 0) | init owner (rest) ===
    if (b == 0) {
        for (int c = tid; c < NCPAD; c += TBLK) s_buf[c] = 0;
        if (tid < 5) g_acc[tid] = 0.0f;
        if (tid == 5) g_qtail = 0;
        __syncthreads();
        // histogram (+ cache cell ids)
        #pragma unroll
        for (int r = 0; r < MAXN / TBLK; ++r) {
            int i = tid + r * TBLK;
            if (i < n) {
                const float* g = gt + (size_t)i * 7;
                float x = __ldg(g), y = __ldg(g + 1), z = __ldg(g + 2);
                int c = (cell1(z) * GRID1 + cell1(y)) * GRID1 + cell1(x);
                g_cellof[i] = c;
                atomicAdd(&s_buf[c], 1);
            }
        }
        __syncthreads();
        // exclusive scan, 32 cells/thread, 8 warps
        int base = tid * 32;
        int s = 0;
        #pragma unroll
        for (int k = 0; k < 32; ++k) s += s_buf[base + k];
        int x = s;
        #pragma unroll
        for (int o = 1; o < 32; o <<= 1) {
            int y = __shfl_up_sync(0xFFFFFFFFu, x, o);
            if (lane >= o) x += y;
        }
        if (lane == 31) s_warp[wid] = x;
        __syncthreads();
        if (wid == 0) {
            int w = (lane < 8) ? s_warp[lane] : 0;
            int xx = w;
            #pragma unroll
            for (int o = 1; o < 8; o <<= 1) {
                int y = __shfl_up_sync(0xFFFFFFFFu, xx, o);
                if (lane >= o) xx += y;
            }
            if (lane < 8) s_warp[lane] = xx - w;
        }
        __syncthreads();
        int run = s_warp[wid] + (x - s);
        #pragma unroll
        for (int k = 0; k < 32; ++k) {
            int t = s_buf[base + k];
            g_cellstart[base + k] = run;
            s_buf[base + k] = run;         // cursor
            run += t;
        }
        if (tid == TBLK - 1) g_cellstart[NCPAD] = run;
        __syncthreads();
        // scatter packed float4 (gt xyz re-reads hit L1/L2)
        #pragma unroll
        for (int r = 0; r < MAXN / TBLK; ++r) {
            int i = tid + r * TBLK;
            if (i < n) {
                const float* g = gt + (size_t)i * 7;
                float x3 = __ldg(g), y3 = __ldg(g + 1), z3 = __ldg(g + 2);
                int c = g_cellof[i];
                int p = atomicAdd(&s_buf[c], 1);
                g_cellxyz[p] = make_float4(x3, y3, z3, __int_as_float(i));
            }
        }
    } else {
        int t2 = (b - 1) * TBLK + tid;
        if (t2 < n) g_owner[t2] = 0x7FFFFFFF;
    }
    gsync(0);

    // ================= phase B: query + fused register sort =================
    // Per-dim neighborhood [cell1(px-5), cell1(px+5)] is a superset (monotone
    // f32 ops); exact dsq<25 test -> identical candidate set to brute force.
    int i = tid * GBLK + b;                // stripe rows across all SMs
    if (i < m) {
        float px = pred[i * 7 + 0], py = pred[i * 7 + 1], pz = pred[i * 7 + 2];
        u64 a[KC];
        #pragma unroll
        for (int k = 0; k < KC; ++k) a[k] = ~0ull;
        int cnt = 0;
        int x0 = cell1(px - 5.0f), x1 = cell1(px + 5.0f);
        int y0 = cell1(py - 5.0f), y1 = cell1(py + 5.0f);
        int z0 = cell1(pz - 5.0f), z1 = cell1(pz + 5.0f);
        for (int zz = z0; zz <= z1; ++zz) {
            for (int yy = y0; yy <= y1; ++yy) {
                int rowc = (zz * GRID1 + yy) * GRID1;
                int s = __ldg(&g_cellstart[rowc + x0]);
                int e = __ldg(&g_cellstart[rowc + x1 + 1]);
                for (int t = s; t < e; ++t) {
                    float4 v = __ldg(&g_cellxyz[t]);
                    float dx = px - v.x, dy = py - v.y, dz = pz - v.z;
                    float d = fmaf(dx, dx, fmaf(dy, dy, dz * dz));
                    if (d < 25.0f) {
                        u64 key = ((u64)__float_as_uint(d) << 32)
                                | (unsigned)__float_as_int(v.w);
                        ++cnt;
                        #pragma unroll
                        for (int k = 0; k < KC; ++k) {   // sorted min-sweep
                            u64 mn = min(a[k], key);
                            key = a[k] ^ key ^ mn;
                            a[k] = mn;
                        }
                    }
                }
            }
        }
        cnt = min(cnt, KC);
        unsigned c7[7];
        #pragma unroll
        for (int k = 0; k < 7; ++k) c7[k] = (unsigned)(a[k] & 0xFFFFu);
        uint4 rv;
        rv.x = (unsigned)cnt | (c7[0] << 16);
        rv.y = c7[1] | (c7[2] << 16);
        rv.z = c7[3] | (c7[4] << 16);
        rv.w = c7[5] | (c7[6] << 16);
        g_row[i] = rv;
        for (int k = 7; k < cnt; ++k)
            g_sorted[(size_t)i * CSTRIDE + k] = (unsigned short)(a[k] & 0xFFFFu);
    }
    gsync(1);

    // ================= phase C1: parallel initial chain pass ================
    // owner[j] = all-time min proposing row (monotone atomicMin). A winner
    // that displaces a parked row pushes it into the queue. Fixed point ==
    // sequential greedy (verified rounds 1-5). <=1 outstanding entry/row.
    if (i < m) {
        uint4 rv = __ldg(&g_row[i]);
        int c = (int)(rv.x & 0xFFFFu);
        int p = 0;
        while (p < c) {
            int j = cand_at(rv, p, i);
            int old = atomicMin(&g_owner[j], i);
            if (old < i) { ++p; continue; }
            if (old != 0x7FFFFFFF) {
                int q = atomicAdd(&g_qtail, 1);
                g_queue[q & (MAXM - 1)] = (unsigned short)old;
            }
            break;
        }
        g_ptr[i] = (unsigned char)p;
    }
    gsync(2);

    // ================= phase C2: block 0 drains displacement queue ==========
    if (b == 0) {
        for (int c = tid; c < n; c += TBLK) s_buf[c] = g_owner[c];
        __syncthreads();
        int from = 0;
        for (;;) {
            if (tid == 0) s_t = *((volatile int*)&g_qtail);
            __syncthreads();
            int t = s_t;
            if (from >= t) break;
            for (int idx = from + tid; idx < t; idx += TBLK) {
                int ii = (int)g_queue[idx & (MAXM - 1)];
                uint4 rv = __ldg(&g_row[ii]);
                int c = (int)(rv.x & 0xFFFFu);
                int p = (int)__ldcg(&g_ptr[ii]);   // L2 (cross-SM writes)
                while (p < c) {
                    int j = cand_at(rv, p, ii);
                    int old = atomicMin(&s_buf[j], ii);
                    if (old < ii) { ++p; continue; }
                    if (old != 0x7FFFFFFF) {
                        int q = atomicAdd(&g_qtail, 1);
                        g_queue[q & (MAXM - 1)] = (unsigned short)old;
                    }
                    break;
                }
                g_ptr[ii] = (unsigned char)p;
            }
            from = t;
            __syncthreads();
        }
    }
    gsync(3);

    // ================= phase D: loss ========================================
    float sc = 0.f, ss = 0.f, so = 0.f, si = 0.f, cf = 0.f;
    if (i < m) {
        uint4 rv = __ldg(&g_row[i]);
        int c = (int)(rv.x & 0xFFFFu);
        int p = (int)__ldcg(&g_ptr[i]);            // L2 (C2 may have updated)
        if (p < c) {
            int j = cand_at(rv, p, i);
            cf = 1.0f;
            const float* pp = pred + (size_t)i * 7;
            const float* gg = gt + (size_t)j * 7;
            sc = sl1(pp[0] - gg[0]) + sl1(pp[1] - gg[1]) + sl1(pp[2] - gg[2]);
            ss = sl1(pp[3] - gg[3]) + sl1(pp[4] - gg[4]) + sl1(pp[5] - gg[5]);
            float dth = pp[6] - gg[6];
            dth = fmaf(-rintf(dth * 0.15915494309f), 6.283185307f, dth);
            so = sl1(dth);                          // sl1(|.|) symmetric: wrap dir irrelevant
            float x1 = pp[0], y1 = pp[1], l1 = pp[3], w1 = pp[4];
            float x2 = gg[0], y2 = gg[1], l2 = gg[3], w2 = gg[4];
            float iw = fminf(x1 + l1 * 0.5f, x2 + l2 * 0.5f)
                     - fmaxf(x1 - l1 * 0.5f, x2 - l2 * 0.5f);
            iw = fmaxf(iw, 0.0f);
            float ih = fminf(y1 + w1 * 0.5f, y2 + w2 * 0.5f)
                     - fmaxf(y1 - w1 * 0.5f, y2 - w2 * 0.5f);
            ih = fmaxf(ih, 0.0f);
            float inter = iw * ih;
            float uni = l1 * w1 + l2 * w2 - inter;
            si = 1.0f - inter / (uni + 1e-6f);
        }
    }
    #pragma unroll
    for (int o = 16; o; o >>= 1) {
        sc += __shfl_down_sync(0xFFFFFFFFu, sc, o);
        ss += __shfl_down_sync(0xFFFFFFFFu, ss, o);
        so += __shfl_down_sync(0xFFFFFFFFu, so, o);
        si += __shfl_down_sync(0xFFFFFFFFu, si, o);
        cf += __shfl_down_sync(0xFFFFFFFFu, cf, o);
    }
    if (lane == 0 && (sc != 0.f || ss != 0.f || so != 0.f || si != 0.f || cf != 0.f)) {
        atomicAdd(&g_acc[0], sc);
        atomicAdd(&g_acc[1], ss);
        atomicAdd(&g_acc[2], so);
        atomicAdd(&g_acc[3], si);
        atomicAdd(&g_acc[4], cf);
    }
    gsync(4);

    if (b == 0 && tid == 0) {
        float a0 = atomicAdd(&g_acc[0], 0.0f);
        float a1 = atomicAdd(&g_acc[1], 0.0f);
        float a2 = atomicAdd(&g_acc[2], 0.0f);
        float a3 = atomicAdd(&g_acc[3], 0.0f);
        float a4 = atomicAdd(&g_acc[4], 0.0f);
        float k  = fmaxf(a4, 1.0f);
        out[0] = a0 / (3.0f * k) + 0.5f * (a1 / (3.0f * k) + a2 / k)
               + 2.0f * (a3 / k);
    }
}

// ---------------- launch ----------------
extern "C" void kernel_launch(void* const* d_in, const int* in_sizes, int n_in,
                              void* d_out, int out_size) {
    const float* pred = (const float*)d_in[0];
    const float* gt   = (const float*)d_in[1];
    int m = in_sizes[0] / 7;
    int n = in_sizes[1] / 7;
    fused_kernel<<<GBLK, TBLK>>>(pred, gt, m, n, (float*)d_out);
}

// round 7
// speedup vs baseline: 1.3049x; 1.3049x over previous
#include <cuda_runtime.h>
#include <cstdint>

#define GRID1   20
#define NCPAD   8192
#define CAP     16             // bucket capacity (overflow P ~ 2e-12)
#define KC      24             // per-row candidate cap (verified vs brute force)
#define CSTRIDE 32
#define MAXM    8192
#define MAXN    8192
#define GBLK    128
#define TBLK    256

typedef unsigned long long u64;

// ---------------- device scratch (no allocations allowed) ----------------
__device__ int            g_cellcnt[NCPAD];          // zero-init; phase D re-zeros
__device__ float4         g_bucket[NCPAD * CAP];     // (x,y,z,bitcast id)
__device__ uint4          g_row[MAXM];               // cnt | first 7 sorted candidates
__device__ unsigned short g_sorted[MAXM * CSTRIDE];  // overflow (pos >= 7)
__device__ int            g_owner[MAXN];
__device__ unsigned char  g_ptr[MAXM];
__device__ unsigned short g_queue[MAXM];             // ring (<=1 outstanding per row)
__device__ int            g_qtail;                   // zero-init; phase D re-zeros
__device__ float          g_acc[5];
__device__ volatile unsigned g_bcnt[4];              // zero-init; self-resetting
__device__ volatile unsigned g_bgen[4];              // monotonic generation

__device__ __forceinline__ int cell1(float x) {
    int c = (int)floorf(x * 0.2f);
    return min(max(c, 0), GRID1 - 1);
}

// Generation-based grid barrier; all GBLK blocks co-resident (128 <= 148 SMs).
__device__ __forceinline__ void gsync(int k) {
    __syncthreads();
    if (threadIdx.x == 0) {
        unsigned old = g_bgen[k];
        __threadfence();
        unsigned a = atomicAdd((unsigned*)&g_bcnt[k], 1u);
        if (a == GBLK - 1) {
            g_bcnt[k] = 0;
            __threadfence();
            atomicAdd((unsigned*)&g_bgen[k], 1u);
        } else {
            while (g_bgen[k] == old) __nanosleep(32);
        }
    }
    __syncthreads();
    __threadfence();
}

__device__ __forceinline__ int cand_at(uint4 rv, int p, int i) {
    if (p < 7) {
        unsigned w = (p == 0) ? rv.x : (p < 3) ? rv.y : (p < 5) ? rv.z : rv.w;
        int sh = (p == 0) ? 16 : ((p & 1) ? 0 : 16);
        return (int)((w >> sh) & 0xFFFFu);
    }
    return (int)g_sorted[(size_t)i * CSTRIDE + p];
}

__device__ __forceinline__ float sl1(float x) {
    float a = fabsf(x);
    return (a < 1.0f) ? 0.5f * a * a : a - 0.5f;
}

__global__ void __launch_bounds__(TBLK)
fused_kernel(const float* __restrict__ pred, const float* __restrict__ gt,
             int m, int n, float* __restrict__ out) {
    __shared__ int s_t;
    int b = blockIdx.x, tid = threadIdx.x;
    int lane = tid & 31;
    int gtid = b * TBLK + tid;

    // ========== phase A: parallel bucket build + owner/acc init ==========
    if (gtid < 5) g_acc[gtid] = 0.0f;
    if (gtid < n) {
        g_owner[gtid] = 0x7FFFFFFF;
        const float* g = gt + (size_t)gtid * 7;
        float x = __ldg(g), y = __ldg(g + 1), z = __ldg(g + 2);
        int c = (cell1(z) * GRID1 + cell1(y)) * GRID1 + cell1(x);
        int slot = atomicAdd(&g_cellcnt[c], 1);
        if (slot < CAP)
            g_bucket[c * CAP + slot] = make_float4(x, y, z, __int_as_float(gtid));
    }
    gsync(0);

    // ========== phase B+C1: query + fused sort + initial chain pass ==========
    // Per-dim neighborhood [cell1(px-5), cell1(px+5)] is a superset (monotone
    // f32 ops); exact dsq<25 -> identical candidate set to brute force.
    // Candidates sorted by (fbits(dsq)<<32 | j) via register min-sweep ->
    // exact serial-argmin order (verified rounds 1-6).
    int R = (m + GBLK - 1) / GBLK;           // rows per block (64)
    int i = b * R + tid;
    bool rowv = (tid < R) && (i < m);
    if (rowv) {
        float px = pred[i * 7 + 0], py = pred[i * 7 + 1], pz = pred[i * 7 + 2];
        u64 a[KC];
        #pragma unroll
        for (int k = 0; k < KC; ++k) a[k] = ~0ull;
        int cnt = 0;
        int x0 = cell1(px - 5.0f), x1 = cell1(px + 5.0f);
        int y0 = cell1(py - 5.0f), y1 = cell1(py + 5.0f);
        int z0 = cell1(pz - 5.0f), z1 = cell1(pz + 5.0f);
        for (int zz = z0; zz <= z1; ++zz) {
            for (int yy = y0; yy <= y1; ++yy) {
                int rowc = (zz * GRID1 + yy) * GRID1;
                for (int xx = x0; xx <= x1; ++xx) {
                    int c = rowc + xx;
                    int cc = min(__ldg(&g_cellcnt[c]), CAP);
                    const float4* bp = &g_bucket[c * CAP];
                    for (int t = 0; t < cc; ++t) {
                        float4 v = __ldg(bp + t);
                        float dx = px - v.x, dy = py - v.y, dz = pz - v.z;
                        float d = fmaf(dx, dx, fmaf(dy, dy, dz * dz));
                        if (d < 25.0f) {
                            u64 key = ((u64)__float_as_uint(d) << 32)
                                    | (unsigned)__float_as_int(v.w);
                            ++cnt;
                            #pragma unroll
                            for (int k = 0; k < KC; ++k) {   // sorted min-sweep
                                u64 mn = min(a[k], key);
                                key = a[k] ^ key ^ mn;
                                a[k] = mn;
                            }
                        }
                    }
                }
            }
        }
        cnt = min(cnt, KC);
        unsigned c7[7];
        #pragma unroll
        for (int k = 0; k < 7; ++k) c7[k] = (unsigned)(a[k] & 0xFFFFu);
        uint4 rv;
        rv.x = (unsigned)cnt | (c7[0] << 16);
        rv.y = c7[1] | (c7[2] << 16);
        rv.z = c7[3] | (c7[4] << 16);
        rv.w = c7[5] | (c7[6] << 16);
        g_row[i] = rv;
        for (int k = 7; k < cnt; ++k)
            g_sorted[(size_t)i * CSTRIDE + k] = (unsigned short)(a[k] & 0xFFFFu);

        // ---- C1: initial chain (owner monotone via atomicMin; displaced
        // parked rows go to the queue; fixed point == sequential greedy) ----
        int p = 0;
        while (p < cnt) {
            int j = cand_at(rv, p, i);
            int old = atomicMin(&g_owner[j], i);
            if (old < i) { ++p; continue; }
            if (old != 0x7FFFFFFF) {
                int q = atomicAdd(&g_qtail, 1);
                g_queue[q & (MAXM - 1)] = (unsigned short)old;
            }
            break;
        }
        g_ptr[i] = (unsigned char)p;
    }
    gsync(1);

    // ========== phase C2: block 0 drains displacement queue ==========
    if (b == 0) {
        int from = 0;
        for (;;) {
            if (tid == 0) s_t = *((volatile int*)&g_qtail);
            __syncthreads();
            int t = s_t;
            if (from >= t) break;
            for (int idx = from + tid; idx < t; idx += TBLK) {
                int ii = (int)g_queue[idx & (MAXM - 1)];
                uint4 rv = __ldg(&g_row[ii]);
                int c = (int)(rv.x & 0xFFFFu);
                int p = (int)__ldcg(&g_ptr[ii]);
                while (p < c) {
                    int j = cand_at(rv, p, ii);
                    int old = atomicMin(&g_owner[j], ii);
                    if (old < ii) { ++p; continue; }
                    if (old != 0x7FFFFFFF) {
                        int q = atomicAdd(&g_qtail, 1);
                        g_queue[q & (MAXM - 1)] = (unsigned short)old;
                    }
                    break;
                }
                g_ptr[ii] = (unsigned char)p;
            }
            from = t;
            __syncthreads();
        }
    }
    gsync(2);

    // ========== phase D: loss + cleanup for next replay ==========
    if (gtid < NCPAD) g_cellcnt[gtid] = 0;
    if (gtid == 0) g_qtail = 0;

    float sc = 0.f, ss = 0.f, so = 0.f, si = 0.f, cf = 0.f;
    if (rowv) {
        uint4 rv = __ldg(&g_row[i]);
        int c = (int)(rv.x & 0xFFFFu);
        int p = (int)__ldcg(&g_ptr[i]);          // C2 (other SM) may have updated
        if (p < c) {
            int j = cand_at(rv, p, i);
            cf = 1.0f;
            const float* pp = pred + (size_t)i * 7;
            const float* gg = gt + (size_t)j * 7;
            sc = sl1(pp[0] - gg[0]) + sl1(pp[1] - gg[1]) + sl1(pp[2] - gg[2]);
            ss = sl1(pp[3] - gg[3]) + sl1(pp[4] - gg[4]) + sl1(pp[5] - gg[5]);
            float dth = pp[6] - gg[6];
            dth = fmaf(-rintf(dth * 0.15915494309f), 6.283185307f, dth);
            so = sl1(dth);                       // sl1(|.|) symmetric: wrap dir irrelevant
            float x1 = pp[0], y1 = pp[1], l1 = pp[3], w1 = pp[4];
            float x2 = gg[0], y2 = gg[1], l2 = gg[3], w2 = gg[4];
            float iw = fminf(x1 + l1 * 0.5f, x2 + l2 * 0.5f)
                     - fmaxf(x1 - l1 * 0.5f, x2 - l2 * 0.5f);
            iw = fmaxf(iw, 0.0f);
            float ih = fminf(y1 + w1 * 0.5f, y2 + w2 * 0.5f)
                     - fmaxf(y1 - w1 * 0.5f, y2 - w2 * 0.5f);
            ih = fmaxf(ih, 0.0f);
            float inter = iw * ih;
            float uni = l1 * w1 + l2 * w2 - inter;
            si = 1.0f - inter / (uni + 1e-6f);
        }
    }
    #pragma unroll
    for (int o = 16; o; o >>= 1) {
        sc += __shfl_down_sync(0xFFFFFFFFu, sc, o);
        ss += __shfl_down_sync(0xFFFFFFFFu, ss, o);
        so += __shfl_down_sync(0xFFFFFFFFu, so, o);
        si += __shfl_down_sync(0xFFFFFFFFu, si, o);
        cf += __shfl_down_sync(0xFFFFFFFFu, cf, o);
    }
    if (lane == 0 && cf != 0.0f) {
        atomicAdd(&g_acc[0], sc);
        atomicAdd(&g_acc[1], ss);
        atomicAdd(&g_acc[2], so);
        atomicAdd(&g_acc[3], si);
        atomicAdd(&g_acc[4], cf);
    }

    // ========== finalize: arrive-only; last arriver writes out ==========
    __syncthreads();
    if (tid == 0) {
        __threadfence();
        unsigned a = atomicAdd((unsigned*)&g_bcnt[3], 1u);
        if (a == GBLK - 1) {
            g_bcnt[3] = 0;
            float a0 = atomicAdd(&g_acc[0], 0.0f);
            float a1 = atomicAdd(&g_acc[1], 0.0f);
            float a2 = atomicAdd(&g_acc[2], 0.0f);
            float a3 = atomicAdd(&g_acc[3], 0.0f);
            float a4 = atomicAdd(&g_acc[4], 0.0f);
            float k  = fmaxf(a4, 1.0f);
            out[0] = a0 / (3.0f * k) + 0.5f * (a1 / (3.0f * k) + a2 / k)
                   + 2.0f * (a3 / k);
        }
    }
}

// ---------------- launch ----------------
extern "C" void kernel_launch(void* const* d_in, const int* in_sizes, int n_in,
                              void* d_out, int out_size) {
    const float* pred = (const float*)d_in[0];
    const float* gt   = (const float*)d_in[1];
    int m = in_sizes[0] / 7;
    int n = in_sizes[1] / 7;
    fused_kernel<<<GBLK, TBLK>>>(pred, gt, m, n, (float*)d_out);
}

// round 8
// speedup vs baseline: 1.7653x; 1.3528x over previous
#include <cuda_runtime.h>
#include <cstdint>

#define GRID1   20
#define NCPAD   8192
#define CAP     16             // bucket capacity (overflow P ~ 2e-12)
#define KC      24             // per-row candidate cap (verified vs brute force)
#define CSTRIDE 32
#define MAXM    8192
#define MAXN    8192
#define GBLK    128
#define TBLK    64
#define OWNER_INIT 0x7FFFFFFF

typedef unsigned long long u64;

// ---------------- device scratch (no allocations allowed) ----------------
__device__ int            g_cellcnt[NCPAD];          // zero-init; phase D re-zeros
__device__ float4         g_bucket[NCPAD * CAP];     // (x,y,z,bitcast id)
__device__ uint4          g_row[MAXM];               // cnt | first 7 sorted candidates
__device__ unsigned short g_sorted[MAXM * CSTRIDE];  // overflow (pos >= 7)
__device__ int            g_owner[MAXN];             // packed (row<<5 | pos)
__device__ float          g_acc[5];
__device__ volatile unsigned g_bcnt[4];              // zero-init; self-resetting
__device__ volatile unsigned g_bgen[4];              // monotonic generation

__device__ __forceinline__ int cell1(float x) {
    int c = (int)floorf(x * 0.2f);
    return min(max(c, 0), GRID1 - 1);
}

// Generation-based grid barrier; all GBLK blocks co-resident (128 <= 148 SMs).
__device__ __forceinline__ void gsync(int k) {
    __syncthreads();
    if (threadIdx.x == 0) {
        unsigned old = g_bgen[k];
        __threadfence();
        unsigned a = atomicAdd((unsigned*)&g_bcnt[k], 1u);
        if (a == GBLK - 1) {
            g_bcnt[k] = 0;
            __threadfence();
            atomicAdd((unsigned*)&g_bgen[k], 1u);
        } else {
            while (g_bgen[k] == old) __nanosleep(32);
        }
    }
    __syncthreads();
    __threadfence();
}

// candidate p of a row given its packed uint4; own=true may use L1 (own writes)
__device__ __forceinline__ int cand_at(uint4 rv, int p, int row, bool own) {
    if (p < 7) {
        unsigned w = (p == 0) ? rv.x : (p < 3) ? rv.y : (p < 5) ? rv.z : rv.w;
        int sh = (p == 0) ? 16 : ((p & 1) ? 0 : 16);
        return (int)((w >> sh) & 0xFFFFu);
    }
    const unsigned short* q = &g_sorted[(size_t)row * CSTRIDE + p];
    return own ? (int)*q : (int)__ldcg(q);
}

__device__ __forceinline__ float sl1(float x) {
    float a = fabsf(x);
    return (a < 1.0f) ? 0.5f * a * a : a - 0.5f;
}

__global__ void __launch_bounds__(TBLK)
fused_kernel(const float* __restrict__ pred, const float* __restrict__ gt,
             int m, int n, float* __restrict__ out) {
    int b = blockIdx.x, tid = threadIdx.x;
    int lane = tid & 31;
    int i = b * TBLK + tid;                 // one row / one gt per thread

    // ========== phase A: bucket build + owner/acc init (fully parallel) ====
    if (i < 5) g_acc[i] = 0.0f;
    if (i < n) {
        g_owner[i] = OWNER_INIT;
        const float* g = gt + (size_t)i * 7;
        float x = __ldg(g), y = __ldg(g + 1), z = __ldg(g + 2);
        int c = (cell1(z) * GRID1 + cell1(y)) * GRID1 + cell1(x);
        int slot = atomicAdd(&g_cellcnt[c], 1);
        if (slot < CAP)
            g_bucket[c * CAP + slot] = make_float4(x, y, z, __int_as_float(i));
    }
    gsync(0);

    // ========== phase B: query, MLP-batched, sort-at-end ====================
    // Per-dim neighborhood [cell1(px-5), cell1(px+5)] spans <=3 consecutive
    // cells and is a superset (monotone f32 ops); exact dsq<25 test ->
    // identical candidate set to brute force. Keys (fbits(dsq)<<32 | j)
    // sorted ascending == exact serial-argmin order (verified rounds 1-7).
    uint4 rv = make_uint4(0, 0, 0, 0);
    int   cnt = 0;
    if (i < m) {
        float px = pred[i * 7 + 0], py = pred[i * 7 + 1], pz = pred[i * 7 + 2];
        u64 a[KC];                           // local mem; appended unsorted
        int x0 = cell1(px - 5.0f), x1 = cell1(px + 5.0f);
        int y0 = cell1(py - 5.0f), y1 = cell1(py + 5.0f);
        int z0 = cell1(pz - 5.0f), z1 = cell1(pz + 5.0f);
        for (int zz = z0; zz <= z1; ++zz) {
            int cc[9], ci[9];
            float4 v0[9];
            // wave 1: 9 independent count loads
            #pragma unroll
            for (int dy = 0; dy < 3; ++dy) {
                int yy = y0 + dy;
                bool ay = (yy <= y1);
                int rowc = (zz * GRID1 + yy) * GRID1;
                #pragma unroll
                for (int dx = 0; dx < 3; ++dx) {
                    int k = dy * 3 + dx;
                    int xx = x0 + dx;
                    ci[k] = rowc + xx;
                    cc[k] = (ay && xx <= x1) ? __ldg(&g_cellcnt[ci[k]]) : 0;
                }
            }
            // wave 2: 9 independent first-entry loads
            #pragma unroll
            for (int k = 0; k < 9; ++k)
                if (cc[k] > 0) v0[k] = __ldg(&g_bucket[ci[k] * CAP]);
            // process (rare second entries loaded on demand)
            #pragma unroll
            for (int k = 0; k < 9; ++k) {
                int c2 = min(cc[k], CAP);
                for (int t = 0; t < c2; ++t) {
                    float4 v = (t == 0) ? v0[k]
                                        : __ldg(&g_bucket[ci[k] * CAP + t]);
                    float dx = px - v.x, dy = py - v.y, dz = pz - v.z;
                    float d = fmaf(dx, dx, fmaf(dy, dy, dz * dz));
                    if (d < 25.0f) {
                        if (cnt < KC)
                            a[cnt] = ((u64)__float_as_uint(d) << 32)
                                   | (unsigned)__float_as_int(v.w);
                        ++cnt;
                    }
                }
            }
        }
        cnt = min(cnt, KC);
        for (int c = 1; c < cnt; ++c) {      // insertion sort (cnt ~4-5)
            u64 v = a[c];
            int d = c;
            while (d > 0 && a[d - 1] > v) { a[d] = a[d - 1]; --d; }
            a[d] = v;
        }
        unsigned c7[7];
        #pragma unroll
        for (int k = 0; k < 7; ++k)
            c7[k] = (k < cnt) ? (unsigned)(a[k] & 0xFFFFu) : 0u;
        rv.x = (unsigned)cnt | (c7[0] << 16);
        rv.y = c7[1] | (c7[2] << 16);
        rv.z = c7[3] | (c7[4] << 16);
        rv.w = c7[5] | (c7[6] << 16);
        g_row[i] = rv;
        for (int k = 7; k < cnt; ++k)
            g_sorted[(size_t)i * CSTRIDE + k] = (unsigned short)(a[k] & 0xFFFFu);
    }
    __threadfence();   // release g_row/g_sorted before owner atomics

    // ========== phase C: eager-chain greedy matcher (no barriers) ==========
    // owner[j] = min packed (row<<5|pos) ever proposed (atomicMin, monotone).
    // Lexicographic packed order == row priority. On displacement, the winner
    // continues the displaced row's walk itself (position recovered from the
    // returned packed value) -> no queue, no sync. Fixed point is order-
    // independent == sequential greedy (verified rounds 3-7). Cross-row
    // g_row/g_sorted reads ordered by fence->atomic->atomic->ldcg chain.
    if (i < m) {
        int cur = i, p = 0, ccnt = cnt;
        uint4 crv = rv;
        bool own = true;
        while (p < ccnt) {
            int j = cand_at(crv, p, cur, own);
            int my = (cur << 5) | p;
            int old = atomicMin(&g_owner[j], my);
            if (old < my) { ++p; continue; }     // better owner: advance
            if (old == OWNER_INIT) break;        // parked in empty slot: done
            cur = old >> 5;                      // continue displaced row
            p = (old & 31) + 1;
            crv = make_uint4(__ldcg(&g_row[cur].x), __ldcg(&g_row[cur].y),
                             __ldcg(&g_row[cur].z), __ldcg(&g_row[cur].w));
            ccnt = (int)(crv.x & 0xFFFFu);
            own = false;
        }
    }
    gsync(1);

    // ========== phase D: match recovery + loss + cleanup ==================
    if (i < NCPAD) g_cellcnt[i] = 0;             // zero-state for next replay

    float sc = 0.f, ss = 0.f, so = 0.f, si = 0.f, cf = 0.f;
    if (i < m) {
        int match = -1;
        for (int p = 0; p < cnt; ++p) {          // final owner row < i for all
            int j = cand_at(rv, p, i, true);     // pre-park positions
            int v = __ldcg(&g_owner[j]);         // atomics live in L2
            if ((v >> 5) == i) { match = j; break; }
            if (v > ((i << 5) | p)) break;       // (unreachable at fixed point)
        }
        if (match >= 0) {
            int j = match;
            cf = 1.0f;
            const float* pp = pred + (size_t)i * 7;
            const float* gg = gt + (size_t)j * 7;
            sc = sl1(pp[0] - gg[0]) + sl1(pp[1] - gg[1]) + sl1(pp[2] - gg[2]);
            ss = sl1(pp[3] - gg[3]) + sl1(pp[4] - gg[4]) + sl1(pp[5] - gg[5]);
            float dth = pp[6] - gg[6];
            dth = fmaf(-rintf(dth * 0.15915494309f), 6.283185307f, dth);
            so = sl1(dth);                       // sl1(|.|) symmetric: wrap dir irrelevant
            float x1 = pp[0], y1 = pp[1], l1 = pp[3], w1 = pp[4];
            float x2 = gg[0], y2 = gg[1], l2 = gg[3], w2 = gg[4];
            float iw = fminf(x1 + l1 * 0.5f, x2 + l2 * 0.5f)
                     - fmaxf(x1 - l1 * 0.5f, x2 - l2 * 0.5f);
            iw = fmaxf(iw, 0.0f);
            float ih = fminf(y1 + w1 * 0.5f, y2 + w2 * 0.5f)
                     - fmaxf(y1 - w1 * 0.5f, y2 - w2 * 0.5f);
            ih = fmaxf(ih, 0.0f);
            float inter = iw * ih;
            float uni = l1 * w1 + l2 * w2 - inter;
            si = 1.0f - inter / (uni + 1e-6f);
        }
    }
    #pragma unroll
    for (int o = 16; o; o >>= 1) {
        sc += __shfl_down_sync(0xFFFFFFFFu, sc, o);
        ss += __shfl_down_sync(0xFFFFFFFFu, ss, o);
        so += __shfl_down_sync(0xFFFFFFFFu, so, o);
        si += __shfl_down_sync(0xFFFFFFFFu, si, o);
        cf += __shfl_down_sync(0xFFFFFFFFu, cf, o);
    }
    if (lane == 0 && cf != 0.0f) {
        atomicAdd(&g_acc[0], sc);
        atomicAdd(&g_acc[1], ss);
        atomicAdd(&g_acc[2], so);
        atomicAdd(&g_acc[3], si);
        atomicAdd(&g_acc[4], cf);
    }

    // ========== finalize: arrive-only; last arriver writes out =============
    __syncthreads();
    if (tid == 0) {
        __threadfence();
        unsigned a = atomicAdd((unsigned*)&g_bcnt[2], 1u);
        if (a == GBLK - 1) {
            g_bcnt[2] = 0;
            float a0 = atomicAdd(&g_acc[0], 0.0f);
            float a1 = atomicAdd(&g_acc[1], 0.0f);
            float a2 = atomicAdd(&g_acc[2], 0.0f);
            float a3 = atomicAdd(&g_acc[3], 0.0f);
            float a4 = atomicAdd(&g_acc[4], 0.0f);
            float k  = fmaxf(a4, 1.0f);
            out[0] = a0 / (3.0f * k) + 0.5f * (a1 / (3.0f * k) + a2 / k)
                   + 2.0f * (a3 / k);
        }
    }
}

// ---------------- launch ----------------
extern "C" void kernel_launch(void* const* d_in, const int* in_sizes, int n_in,
                              void* d_out, int out_size) {
    const float* pred = (const float*)d_in[0];
    const float* gt   = (const float*)d_in[1];
    int m = in_sizes[0] / 7;
    int n = in_sizes[1] / 7;
    fused_kernel<<<GBLK, TBLK>>>(pred, gt, m, n, (float*)d_out);
}

// round 9
// speedup vs baseline: 1.9308x; 1.0938x over previous
#include <cuda_runtime.h>
#include <cstdint>

#define GRID1   20
#define NCPAD   8192
#define CAP     16             // bucket capacity (overflow P ~ 2e-12)
#define KC      24             // per-row candidate cap (verified vs brute force)
#define CSTRIDE 32
#define MAXM    8192
#define MAXN    8192
#define GBLK    128
#define TBLK    64
#define OWNER_INIT 0x7FFFFFFF

typedef unsigned long long u64;

// ---------------- device scratch (no allocations allowed) ----------------
__device__ int            g_cellcnt[NCPAD];          // zero-init; phase D re-zeros
__device__ float4         g_bucket[NCPAD * CAP];     // (x,y,z,bitcast id)
__device__ uint4          g_row[MAXM];               // cnt | first 7 sorted candidates
__device__ unsigned short g_sorted[MAXM * CSTRIDE];  // overflow (pos >= 7)
__device__ int            g_owner[MAXN];             // packed (row<<5 | pos)
__device__ float          g_acc[5];
__device__ volatile unsigned g_bcnt[4];              // zero-init; self-resetting
__device__ volatile unsigned g_bgen[4];              // monotonic generation

__device__ __forceinline__ int cell1(float x) {
    int c = (int)floorf(x * 0.2f);
    return min(max(c, 0), GRID1 - 1);
}

// Generation-based grid barrier; all GBLK blocks co-resident (128 <= 148 SMs).
// Plain volatile spin (no nanosleep): poll rate self-throttled by L2 latency.
__device__ __forceinline__ void gsync(int k) {
    __syncthreads();
    if (threadIdx.x == 0) {
        unsigned old = g_bgen[k];
        __threadfence();
        unsigned a = atomicAdd((unsigned*)&g_bcnt[k], 1u);
        if (a == GBLK - 1) {
            g_bcnt[k] = 0;
            __threadfence();
            atomicAdd((unsigned*)&g_bgen[k], 1u);
        } else {
            while (g_bgen[k] == old) { }
        }
    }
    __syncthreads();
    __threadfence();
}

// candidate p of a row given its packed uint4; own=true may use L1 (own writes)
__device__ __forceinline__ int cand_at(uint4 rv, int p, int row, bool own) {
    if (p < 7) {
        unsigned w = (p == 0) ? rv.x : (p < 3) ? rv.y : (p < 5) ? rv.z : rv.w;
        int sh = (p == 0) ? 16 : ((p & 1) ? 0 : 16);
        return (int)((w >> sh) & 0xFFFFu);
    }
    const unsigned short* q = &g_sorted[(size_t)row * CSTRIDE + p];
    return own ? (int)*q : (int)__ldcg(q);
}

__device__ __forceinline__ float sl1(float x) {
    float a = fabsf(x);
    return (a < 1.0f) ? 0.5f * a * a : a - 0.5f;
}

__global__ void __launch_bounds__(TBLK)
fused_kernel(const float* __restrict__ pred, const float* __restrict__ gt,
             int m, int n, float* __restrict__ out) {
    int b = blockIdx.x, tid = threadIdx.x;
    int lane = tid & 31;
    int i = b * TBLK + tid;                 // one pred row AND one gt per thread

    // Hoist pred xyz loads: in flight during phase A + barrier.
    float px = 0.f, py = 0.f, pz = 0.f;
    bool rowv = (i < m);
    if (rowv) {
        px = __ldg(&pred[i * 7 + 0]);
        py = __ldg(&pred[i * 7 + 1]);
        pz = __ldg(&pred[i * 7 + 2]);
    }

    // ========== phase A: bucket build + owner/acc init (fully parallel) ====
    float gx = 0.f, gy = 0.f, gz = 0.f;
    if (i < 5) g_acc[i] = 0.0f;
    if (i < n) {
        g_owner[i] = OWNER_INIT;
        const float* g = gt + (size_t)i * 7;
        gx = __ldg(g); gy = __ldg(g + 1); gz = __ldg(g + 2);
        int c = (cell1(gz) * GRID1 + cell1(gy)) * GRID1 + cell1(gx);
        int slot = atomicAdd(&g_cellcnt[c], 1);
        if (slot < CAP)
            g_bucket[c * CAP + slot] = make_float4(gx, gy, gz, __int_as_float(i));
    }
    gsync(0);

    // ========== phase B: query — ALL 27 counts + 27 entry0 in ONE wave =====
    // Per-dim neighborhood [cell1(px-5), cell1(px+5)] spans <=3 consecutive
    // cells and is a superset (monotone f32 ops); exact dsq<25 test ->
    // identical candidate set to brute force. Entry0 loads are speculative
    // (in-bounds clamped addresses; values used only when count>0). Keys
    // (fbits(dsq)<<32 | j) sorted ascending == exact serial-argmin order.
    uint4 rv = make_uint4(0, 0, 0, 0);
    int   cnt = 0;
    if (rowv) {
        u64 a[KC];                           // appended unsorted; sorted below
        int x0 = cell1(px - 5.0f), x1 = cell1(px + 5.0f);
        int y0 = cell1(py - 5.0f), y1 = cell1(py + 5.0f);
        int z0 = cell1(pz - 5.0f), z1 = cell1(pz + 5.0f);

        int    cc[27], ci[27];
        float4 v0[27];
        // wave: 27 count loads + 27 speculative entry0 loads (independent)
        #pragma unroll
        for (int dz = 0; dz < 3; ++dz) {
            int zz = z0 + dz;
            #pragma unroll
            for (int dy = 0; dy < 3; ++dy) {
                int yy = y0 + dy;
                #pragma unroll
                for (int dx = 0; dx < 3; ++dx) {
                    int k = (dz * 3 + dy) * 3 + dx;
                    int xx = x0 + dx;
                    bool ok = (zz <= z1) && (yy <= y1) && (xx <= x1);
                    int c = (zz * GRID1 + yy) * GRID1 + xx;
                    c = min(c, NCPAD - 1);           // clamp: always in-bounds
                    ci[k] = c;
                    cc[k] = ok ? __ldg(&g_cellcnt[c]) : 0;
                }
            }
        }
        #pragma unroll
        for (int k = 0; k < 27; ++k) v0[k] = __ldg(&g_bucket[ci[k] * CAP]);

        #pragma unroll
        for (int k = 0; k < 27; ++k) {
            int c2 = min(cc[k], CAP);
            for (int t = 0; t < c2; ++t) {           // c2>1 rare (mean ~1)
                float4 v = (t == 0) ? v0[k] : __ldg(&g_bucket[ci[k] * CAP + t]);
                float dx = px - v.x, dy = py - v.y, dz = pz - v.z;
                float d = fmaf(dx, dx, fmaf(dy, dy, dz * dz));
                if (d < 25.0f) {
                    if (cnt < KC)
                        a[cnt] = ((u64)__float_as_uint(d) << 32)
                               | (unsigned)__float_as_int(v.w);
                    ++cnt;
                }
            }
        }
        cnt = min(cnt, KC);
        for (int c = 1; c < cnt; ++c) {              // insertion sort (cnt ~4-5)
            u64 v = a[c];
            int d = c;
            while (d > 0 && a[d - 1] > v) { a[d] = a[d - 1]; --d; }
            a[d] = v;
        }
        unsigned c7[7];
        #pragma unroll
        for (int k = 0; k < 7; ++k)
            c7[k] = (k < cnt) ? (unsigned)(a[k] & 0xFFFFu) : 0u;
        rv.x = (unsigned)cnt | (c7[0] << 16);
        rv.y = c7[1] | (c7[2] << 16);
        rv.z = c7[3] | (c7[4] << 16);
        rv.w = c7[5] | (c7[6] << 16);
        g_row[i] = rv;
        for (int k = 7; k < cnt; ++k)
            g_sorted[(size_t)i * CSTRIDE + k] = (unsigned short)(a[k] & 0xFFFFu);
    }
    __threadfence();   // release g_row/g_sorted before owner atomics

    // ========== phase C: eager-chain greedy matcher (no barriers) ==========
    // owner[j] = min packed (row<<5|pos) ever proposed (atomicMin, monotone).
    // Packed lexicographic order == row priority. On displacement, the winner
    // continues the displaced row's walk (position from the returned value).
    // Fixed point is order-independent == sequential greedy (rounds 3-8).
    if (rowv) {
        int cur = i, p = 0, ccnt = cnt;
        uint4 crv = rv;
        bool own = true;
        while (p < ccnt) {
            int j = cand_at(crv, p, cur, own);
            int my = (cur << 5) | p;
            int old = atomicMin(&g_owner[j], my);
            if (old < my) { ++p; continue; }     // better owner: advance
            if (old == OWNER_INIT) break;        // parked in empty slot: done
            cur = old >> 5;                      // continue displaced row
            p = (old & 31) + 1;
            crv = __ldcg(&g_row[cur]);
            ccnt = (int)(crv.x & 0xFFFFu);
            own = false;
        }
    }
    gsync(1);

    // ========== phase D: gt-side loss (owner[j]>>5 IS the matched row) =====
    // At fixed point each row owns <=1 gt (a parked entry is only replaced by
    // a strictly smaller packed value, which resumes that row's walk past it),
    // so iterating gts enumerates exactly the matched pairs, once each.
    if (i < NCPAD) g_cellcnt[i] = 0;             // zero-state for next replay

    float sc = 0.f, ss = 0.f, so = 0.f, si = 0.f, cf = 0.f;
    if (i < n) {
        int v = __ldcg(&g_owner[i]);             // atomics live in L2
        if (v != OWNER_INIT) {
            int r = v >> 5;                      // matched pred row
            cf = 1.0f;
            const float* pp = pred + (size_t)r * 7;
            const float* gg = gt + (size_t)i * 7;
            float p0 = __ldg(pp),     p1 = __ldg(pp + 1), p2 = __ldg(pp + 2);
            float p3 = __ldg(pp + 3), p4 = __ldg(pp + 4), p5 = __ldg(pp + 5);
            float p6 = __ldg(pp + 6);
            float g3 = __ldg(gg + 3), g4 = __ldg(gg + 4), g5 = __ldg(gg + 5);
            float g6 = __ldg(gg + 6);
            sc = sl1(p0 - gx) + sl1(p1 - gy) + sl1(p2 - gz);
            ss = sl1(p3 - g3) + sl1(p4 - g4) + sl1(p5 - g5);
            float dth = p6 - g6;
            dth = fmaf(-rintf(dth * 0.15915494309f), 6.283185307f, dth);
            so = sl1(dth);                       // sl1(|.|) symmetric: wrap dir irrelevant
            float iw = fminf(p0 + p3 * 0.5f, gx + g3 * 0.5f)
                     - fmaxf(p0 - p3 * 0.5f, gx - g3 * 0.5f);
            iw = fmaxf(iw, 0.0f);
            float ih = fminf(p1 + p4 * 0.5f, gy + g4 * 0.5f)
                     - fmaxf(p1 - p4 * 0.5f, gy - g4 * 0.5f);
            ih = fmaxf(ih, 0.0f);
            float inter = iw * ih;
            float uni = p3 * p4 + g3 * g4 - inter;
            si = 1.0f - inter / (uni + 1e-6f);
        }
    }
    #pragma unroll
    for (int o = 16; o; o >>= 1) {
        sc += __shfl_down_sync(0xFFFFFFFFu, sc, o);
        ss += __shfl_down_sync(0xFFFFFFFFu, ss, o);
        so += __shfl_down_sync(0xFFFFFFFFu, so, o);
        si += __shfl_down_sync(0xFFFFFFFFu, si, o);
        cf += __shfl_down_sync(0xFFFFFFFFu, cf, o);
    }
    if (lane == 0 && cf != 0.0f) {
        atomicAdd(&g_acc[0], sc);
        atomicAdd(&g_acc[1], ss);
        atomicAdd(&g_acc[2], so);
        atomicAdd(&g_acc[3], si);
        atomicAdd(&g_acc[4], cf);
    }

    // ========== finalize: arrive-only; last arriver writes out =============
    __syncthreads();
    if (tid == 0) {
        __threadfence();
        unsigned a = atomicAdd((unsigned*)&g_bcnt[2], 1u);
        if (a == GBLK - 1) {
            g_bcnt[2] = 0;
            float a0 = atomicAdd(&g_acc[0], 0.0f);
            float a1 = atomicAdd(&g_acc[1], 0.0f);
            float a2 = atomicAdd(&g_acc[2], 0.0f);
            float a3 = atomicAdd(&g_acc[3], 0.0f);
            float a4 = atomicAdd(&g_acc[4], 0.0f);
            float k  = fmaxf(a4, 1.0f);
            out[0] = a0 / (3.0f * k) + 0.5f * (a1 / (3.0f * k) + a2 / k)
                   + 2.0f * (a3 / k);
        }
    }
}

// ---------------- launch ----------------
extern "C" void kernel_launch(void* const* d_in, const int* in_sizes, int n_in,
                              void* d_out, int out_size) {
    const float* pred = (const float*)d_in[0];
    const float* gt   = (const float*)d_in[1];
    int m = in_sizes[0] / 7;
    int n = in_sizes[1] / 7;
    fused_kernel<<<GBLK, TBLK>>>(pred, gt, m, n, (float*)d_out);
}